// round 1
// baseline (speedup 1.0000x reference)
#include <cuda_runtime.h>
#include <math.h>

#define N_NODES 50000
#define E_MAX   800000
#define DIN     128
#define DH      256
#define DOUT    64
#define LAYERS  4

// ---------------- device scratch (allocation-free) ----------------
__device__ float g_dinv[N_NODES];            // deg then rsqrt(deg)
__device__ float g_norm[E_MAX];              // per-edge weight
__device__ float g_h  [(size_t)N_NODES * DH];
__device__ float g_ht [(size_t)N_NODES * DH];
__device__ float g_agg[(size_t)N_NODES * DH];

// ---------------- degree / norm ----------------
__global__ void k_deg_init(float* deg, int n) {
    int i = blockIdx.x * blockDim.x + threadIdx.x;
    if (i < n) deg[i] = 1.0f;   // self-loop
}

__global__ void k_deg_accum(const int* __restrict__ dst, float* deg, int E) {
    int e = blockIdx.x * blockDim.x + threadIdx.x;
    if (e < E) atomicAdd(&deg[dst[e]], 1.0f);
}

__global__ void k_dinv(float* deg, int n) {
    int i = blockIdx.x * blockDim.x + threadIdx.x;
    if (i < n) {
        float d = deg[i];
        deg[i] = (d > 0.f) ? rsqrtf(d) : 0.f;
    }
}

__global__ void k_norm(const int* __restrict__ src, const int* __restrict__ dst,
                       const float* __restrict__ dinv, float* __restrict__ norm, int E) {
    int e = blockIdx.x * blockDim.x + threadIdx.x;
    if (e < E) norm[e] = dinv[src[e]] * dinv[dst[e]];
}

// ---------------- SGEMM: C[M,N] = A[M,K] @ B[K,N] (+bias) ----------------
// BM=64 BN=64 BK=16, 256 threads, 4x4 microtile
template<bool BIAS>
__global__ void k_sgemm(const float* __restrict__ A, const float* __restrict__ B,
                        const float* __restrict__ bias, float* __restrict__ C,
                        int M, int K, int N) {
    const int BM = 64, BN = 64, BK = 16, TM = 4, TN = 4;
    __shared__ float As[BK][BM];
    __shared__ float Bs[BK][BN];

    int tid = threadIdx.x;                 // 0..255
    int tx  = tid % (BN / TN);             // 0..15
    int ty  = tid / (BN / TN);             // 0..15
    int row0 = blockIdx.y * BM;
    int col0 = blockIdx.x * BN;

    float acc[TM][TN];
    #pragma unroll
    for (int i = 0; i < TM; i++)
        #pragma unroll
        for (int j = 0; j < TN; j++) acc[i][j] = 0.f;

    for (int k0 = 0; k0 < K; k0 += BK) {
        // A tile: BM x BK, stored transposed As[k][m]
        #pragma unroll
        for (int i = tid; i < BM * BK; i += 256) {
            int m = i / BK, k = i % BK;
            int gr = row0 + m;
            As[k][m] = (gr < M) ? A[(size_t)gr * K + k0 + k] : 0.f;
        }
        // B tile: BK x BN
        #pragma unroll
        for (int i = tid; i < BK * BN; i += 256) {
            int k = i / BN, n = i % BN;
            Bs[k][n] = B[(size_t)(k0 + k) * N + col0 + n];
        }
        __syncthreads();

        #pragma unroll
        for (int k = 0; k < BK; k++) {
            float a[TM], b[TN];
            #pragma unroll
            for (int i = 0; i < TM; i++) a[i] = As[k][ty * TM + i];
            #pragma unroll
            for (int j = 0; j < TN; j++) b[j] = Bs[k][tx * TN + j];
            #pragma unroll
            for (int i = 0; i < TM; i++)
                #pragma unroll
                for (int j = 0; j < TN; j++) acc[i][j] += a[i] * b[j];
        }
        __syncthreads();
    }

    #pragma unroll
    for (int i = 0; i < TM; i++) {
        int r = row0 + ty * TM + i;
        if (r >= M) continue;
        #pragma unroll
        for (int j = 0; j < TN; j++) {
            int c = col0 + tx * TN + j;
            float v = acc[i][j];
            if (BIAS) v += bias[c];
            C[(size_t)r * N + c] = v;
        }
    }
}

// ---------------- aggregation ----------------
// agg[i] = ht[i] * dinv[i]^2   (self-loop term)
__global__ void k_selfloop_init(const float* __restrict__ ht, const float* __restrict__ dinv,
                                float* __restrict__ agg, int n) {
    int t = blockIdx.x * blockDim.x + threadIdx.x;    // one float4 per thread
    int total = n * (DH / 4);
    if (t >= total) return;
    int i = t / (DH / 4);
    float w = dinv[i];
    w = w * w;
    float4 v = reinterpret_cast<const float4*>(ht)[t];
    v.x *= w; v.y *= w; v.z *= w; v.w *= w;
    reinterpret_cast<float4*>(agg)[t] = v;
}

// 64 threads per edge, each handles one float4 (4 scalar atomics)
__global__ void k_scatter(const int* __restrict__ src, const int* __restrict__ dst,
                          const float* __restrict__ norm,
                          const float* __restrict__ ht, float* __restrict__ agg, int E) {
    long long t = (long long)blockIdx.x * blockDim.x + threadIdx.x;
    int e = (int)(t >> 6);
    int lane = (int)(t & 63);
    if (e >= E) return;
    int s = src[e], d = dst[e];
    float w = norm[e];
    float4 v = reinterpret_cast<const float4*>(ht + (size_t)s * DH)[lane];
    float* ad = agg + (size_t)d * DH + lane * 4;
    atomicAdd(ad + 0, v.x * w);
    atomicAdd(ad + 1, v.y * w);
    atomicAdd(ad + 2, v.z * w);
    atomicAdd(ad + 3, v.w * w);
}

// h = tanh(agg + b)
__global__ void k_finalize(const float* __restrict__ agg, const float* __restrict__ b,
                           float* __restrict__ h, int n) {
    int t = blockIdx.x * blockDim.x + threadIdx.x;
    int total = n * DH;
    if (t >= total) return;
    int d = t & (DH - 1);
    h[t] = tanhf(agg[t] + b[d]);
}

// ---------------- launcher ----------------
extern "C" void kernel_launch(void* const* d_in, const int* in_sizes, int n_in,
                              void* d_out, int out_size) {
    const float* x      = (const float*)d_in[0];
    const int*   eidx   = (const int*)  d_in[1];
    const float* W_emb  = (const float*)d_in[2];
    const float* b_emb  = (const float*)d_in[3];
    const float* W_conv = (const float*)d_in[4];
    const float* b_conv = (const float*)d_in[5];
    const float* W_out  = (const float*)d_in[6];
    const float* b_out  = (const float*)d_in[7];
    float* out = (float*)d_out;

    int E = in_sizes[1] / 2;
    if (E > E_MAX) E = E_MAX;
    const int* src = eidx;
    const int* dst = eidx + E;
    const int n = N_NODES;

    float *dinv, *norm, *h, *ht, *agg;
    cudaGetSymbolAddress((void**)&dinv, g_dinv);
    cudaGetSymbolAddress((void**)&norm, g_norm);
    cudaGetSymbolAddress((void**)&h,    g_h);
    cudaGetSymbolAddress((void**)&ht,   g_ht);
    cudaGetSymbolAddress((void**)&agg,  g_agg);

    // degree / norm
    k_deg_init <<<(n + 255) / 256, 256>>>(dinv, n);
    k_deg_accum<<<(E + 255) / 256, 256>>>(dst, dinv, E);
    k_dinv     <<<(n + 255) / 256, 256>>>(dinv, n);
    k_norm     <<<(E + 255) / 256, 256>>>(src, dst, dinv, norm, E);

    // embedding: h = x @ W_emb + b_emb   [n,128]@[128,256]
    {
        dim3 grid(DH / 64, (n + 63) / 64);
        k_sgemm<true><<<grid, 256>>>(x, W_emb, b_emb, h, n, DIN, DH);
    }

    // conv layers
    long long scat_threads = (long long)E * 64;
    int scat_blocks = (int)((scat_threads + 255) / 256);
    for (int l = 0; l < LAYERS; l++) {
        const float* W = W_conv + (size_t)l * DH * DH;
        const float* b = b_conv + (size_t)l * DH;
        dim3 grid(DH / 64, (n + 63) / 64);
        k_sgemm<false><<<grid, 256>>>(h, W, nullptr, ht, n, DH, DH);
        k_selfloop_init<<<(n * (DH / 4) + 255) / 256, 256>>>(ht, dinv, agg, n);
        k_scatter<<<scat_blocks, 256>>>(src, dst, norm, ht, agg, E);
        k_finalize<<<(n * DH + 255) / 256, 256>>>(agg, b, h, n);
    }

    // output: out = h @ W_out + b_out   [n,256]@[256,64]
    {
        dim3 grid(DOUT / 64, (n + 63) / 64);
        k_sgemm<true><<<grid, 256>>>(h, W_out, b_out, out, n, DH, DOUT);
    }
}

// round 3
// speedup vs baseline: 1.2281x; 1.2281x over previous
#include <cuda_runtime.h>
#include <math.h>

#define N_NODES 50000
#define E_MAX   800000
#define DIN     128
#define DH      256
#define DOUT    64
#define LAYERS  4

// ---------------- device scratch (allocation-free) ----------------
__device__ float g_dinv[N_NODES];
__device__ float g_norm[E_MAX];
__device__ float g_h  [(size_t)N_NODES * DH];
__device__ float g_ht [(size_t)N_NODES * DH];
__device__ float g_agg[(size_t)N_NODES * DH];

// ---------------- degree / norm ----------------
__global__ void k_deg_init(float* deg, int n) {
    int i = blockIdx.x * blockDim.x + threadIdx.x;
    if (i < n) deg[i] = 1.0f;
}

__global__ void k_deg_accum(const int* __restrict__ dst, float* deg, int E) {
    int e = blockIdx.x * blockDim.x + threadIdx.x;
    if (e < E) atomicAdd(&deg[dst[e]], 1.0f);
}

__global__ void k_dinv(float* deg, int n) {
    int i = blockIdx.x * blockDim.x + threadIdx.x;
    if (i < n) {
        float d = deg[i];
        deg[i] = (d > 0.f) ? rsqrtf(d) : 0.f;
    }
}

__global__ void k_norm(const int* __restrict__ src, const int* __restrict__ dst,
                       const float* __restrict__ dinv, float* __restrict__ norm, int E) {
    int e = blockIdx.x * blockDim.x + threadIdx.x;
    if (e < E) norm[e] = dinv[src[e]] * dinv[dst[e]];
}

// ---------------- SGEMM: C[M,N] = A[M,K] @ B[K,N] ----------------
// BM=128, BK=16, 256 threads. BN/TN templated (128/8 or 64/4).
// Register-prefetch double buffering. Optional bias add; optional fused
// self-loop epilogue: C2[r,c] = C[r,c] * dinv[r]^2.
template<int BN, int TN, bool BIAS, bool SELF>
__global__ __launch_bounds__(256, 2)
void k_sgemm(const float* __restrict__ A, const float* __restrict__ B,
             const float* __restrict__ bias, float* __restrict__ C,
             const float* __restrict__ dinv, float* __restrict__ C2,
             int M, int K, int N) {
    const int BM = 128, BK = 16, TM = 8;
    const int BLDV = (BK * BN / 256) / 4;    // float4s of B per thread (2 or 1)
    __shared__ float As[BK][BM];
    __shared__ float Bs[BK][BN];

    int tid = threadIdx.x;
    int tx = tid % (BN / TN);                // 0..15
    int ty = tid / (BN / TN);                // 0..15
    int row0 = blockIdx.y * BM;
    int col0 = blockIdx.x * BN;

    // A-load mapping: thread -> (row am, k-offset ak), 2 float4 along K
    int am = tid >> 1;                       // 0..127
    int ak = (tid & 1) * 8;                  // 0 or 8

    float acc[TM][TN];
    #pragma unroll
    for (int i = 0; i < TM; i++)
        #pragma unroll
        for (int j = 0; j < TN; j++) acc[i][j] = 0.f;

    float4 pa0, pa1;
    float4 pb[BLDV];

    // prefetch first tile into registers
    {
        int gr = row0 + am;
        if (gr < M) {
            const float* ap = A + (size_t)gr * K + ak;
            pa0 = *reinterpret_cast<const float4*>(ap);
            pa1 = *reinterpret_cast<const float4*>(ap + 4);
        } else {
            pa0 = make_float4(0,0,0,0); pa1 = make_float4(0,0,0,0);
        }
        #pragma unroll
        for (int v = 0; v < BLDV; v++) {
            int lin = (tid + v * 256) * 4;
            int k = lin / BN, nn = lin % BN;
            pb[v] = *reinterpret_cast<const float4*>(B + (size_t)k * N + col0 + nn);
        }
    }

    for (int k0 = 0; k0 < K; k0 += BK) {
        // store prefetched tile to smem
        {
            As[ak + 0][am] = pa0.x; As[ak + 1][am] = pa0.y;
            As[ak + 2][am] = pa0.z; As[ak + 3][am] = pa0.w;
            As[ak + 4][am] = pa1.x; As[ak + 5][am] = pa1.y;
            As[ak + 6][am] = pa1.z; As[ak + 7][am] = pa1.w;
            #pragma unroll
            for (int v = 0; v < BLDV; v++) {
                int lin = (tid + v * 256) * 4;
                int k = lin / BN, nn = lin % BN;
                *reinterpret_cast<float4*>(&Bs[k][nn]) = pb[v];
            }
        }
        __syncthreads();

        // prefetch next tile
        if (k0 + BK < K) {
            int gr = row0 + am;
            if (gr < M) {
                const float* ap = A + (size_t)gr * K + k0 + BK + ak;
                pa0 = *reinterpret_cast<const float4*>(ap);
                pa1 = *reinterpret_cast<const float4*>(ap + 4);
            } else {
                pa0 = make_float4(0,0,0,0); pa1 = make_float4(0,0,0,0);
            }
            #pragma unroll
            for (int v = 0; v < BLDV; v++) {
                int lin = (tid + v * 256) * 4;
                int k = lin / BN, nn = lin % BN;
                pb[v] = *reinterpret_cast<const float4*>(B + (size_t)(k0 + BK + k) * N + col0 + nn);
            }
        }

        // compute
        #pragma unroll
        for (int k = 0; k < BK; k++) {
            float a[TM], b[TN];
            float4 a0 = *reinterpret_cast<const float4*>(&As[k][ty * TM]);
            float4 a1 = *reinterpret_cast<const float4*>(&As[k][ty * TM + 4]);
            a[0]=a0.x; a[1]=a0.y; a[2]=a0.z; a[3]=a0.w;
            a[4]=a1.x; a[5]=a1.y; a[6]=a1.z; a[7]=a1.w;
            float4 b0 = *reinterpret_cast<const float4*>(&Bs[k][tx * TN]);
            b[0]=b0.x; b[1]=b0.y; b[2]=b0.z; b[3]=b0.w;
            if (TN == 8) {
                float4 b1 = *reinterpret_cast<const float4*>(&Bs[k][tx * TN + 4]);
                b[4]=b1.x; b[5]=b1.y; b[6]=b1.z; b[7]=b1.w;
            }
            #pragma unroll
            for (int i = 0; i < TM; i++)
                #pragma unroll
                for (int j = 0; j < TN; j++)
                    acc[i][j] += a[i] * b[j];
        }
        __syncthreads();
    }

    // epilogue
    #pragma unroll
    for (int i = 0; i < TM; i++) {
        int r = row0 + ty * TM + i;
        if (r >= M) continue;
        float w = 0.f;
        if (SELF) { w = dinv[r]; w = w * w; }
        #pragma unroll
        for (int j = 0; j < TN; j += 4) {
            int c = col0 + tx * TN + j;
            float4 v;
            v.x = acc[i][j+0]; v.y = acc[i][j+1];
            v.z = acc[i][j+2]; v.w = acc[i][j+3];
            if (BIAS) {
                v.x += bias[c+0]; v.y += bias[c+1];
                v.z += bias[c+2]; v.w += bias[c+3];
            }
            *reinterpret_cast<float4*>(&C[(size_t)r * N + c]) = v;
            if (SELF) {
                float4 s = make_float4(v.x * w, v.y * w, v.z * w, v.w * w);
                *reinterpret_cast<float4*>(&C2[(size_t)r * N + c]) = s;
            }
        }
    }
}

// ---------------- aggregation ----------------
// 64 threads per edge, each handles one float4 (4 scalar atomics)
__global__ void k_scatter(const int* __restrict__ src, const int* __restrict__ dst,
                          const float* __restrict__ norm,
                          const float* __restrict__ ht, float* __restrict__ agg, int E) {
    long long t = (long long)blockIdx.x * blockDim.x + threadIdx.x;
    int e = (int)(t >> 6);
    int lane = (int)(t & 63);
    if (e >= E) return;
    int s = src[e], d = dst[e];
    float w = norm[e];
    float4 v = reinterpret_cast<const float4*>(ht + (size_t)s * DH)[lane];
    float* ad = agg + (size_t)d * DH + lane * 4;
    atomicAdd(ad + 0, v.x * w);
    atomicAdd(ad + 1, v.y * w);
    atomicAdd(ad + 2, v.z * w);
    atomicAdd(ad + 3, v.w * w);
}

// h = tanh(agg + b)
__global__ void k_finalize(const float* __restrict__ agg, const float* __restrict__ b,
                           float* __restrict__ h, int n) {
    int t = blockIdx.x * blockDim.x + threadIdx.x;
    int total = n * DH;
    if (t >= total) return;
    int d = t & (DH - 1);
    h[t] = tanhf(agg[t] + b[d]);
}

// ---------------- launcher ----------------
extern "C" void kernel_launch(void* const* d_in, const int* in_sizes, int n_in,
                              void* d_out, int out_size) {
    const float* x      = (const float*)d_in[0];
    const int*   eidx   = (const int*)  d_in[1];
    const float* W_emb  = (const float*)d_in[2];
    const float* b_emb  = (const float*)d_in[3];
    const float* W_conv = (const float*)d_in[4];
    const float* b_conv = (const float*)d_in[5];
    const float* W_out  = (const float*)d_in[6];
    const float* b_out  = (const float*)d_in[7];
    float* out = (float*)d_out;

    int E = in_sizes[1] / 2;
    if (E > E_MAX) E = E_MAX;
    const int* src = eidx;
    const int* dst = eidx + E;
    const int n = N_NODES;

    float *dinv, *norm, *h, *ht, *agg;
    cudaGetSymbolAddress((void**)&dinv, g_dinv);
    cudaGetSymbolAddress((void**)&norm, g_norm);
    cudaGetSymbolAddress((void**)&h,    g_h);
    cudaGetSymbolAddress((void**)&ht,   g_ht);
    cudaGetSymbolAddress((void**)&agg,  g_agg);

    // degree / norm
    k_deg_init <<<(n + 255) / 256, 256>>>(dinv, n);
    k_deg_accum<<<(E + 255) / 256, 256>>>(dst, dinv, E);
    k_dinv     <<<(n + 255) / 256, 256>>>(dinv, n);
    k_norm     <<<(E + 255) / 256, 256>>>(src, dst, dinv, norm, E);

    // embedding: h = x @ W_emb + b_emb   [n,128]@[128,256]
    {
        dim3 grid(DH / 128, (n + 127) / 128);
        k_sgemm<128, 8, true, false><<<grid, 256>>>(x, W_emb, b_emb, h, nullptr, nullptr, n, DIN, DH);
    }

    // conv layers
    long long scat_threads = (long long)E * 64;
    int scat_blocks = (int)((scat_threads + 255) / 256);
    for (int l = 0; l < LAYERS; l++) {
        const float* W = W_conv + (size_t)l * DH * DH;
        const float* b = b_conv + (size_t)l * DH;
        dim3 grid(DH / 128, (n + 127) / 128);
        // ht = h @ W ; agg = ht * dinv^2 (fused self-loop)
        k_sgemm<128, 8, false, true><<<grid, 256>>>(h, W, nullptr, ht, dinv, agg, n, DH, DH);
        k_scatter<<<scat_blocks, 256>>>(src, dst, norm, ht, agg, E);
        k_finalize<<<(n * DH + 255) / 256, 256>>>(agg, b, h, n);
    }

    // output: out = h @ W_out + b_out   [n,256]@[256,64]
    {
        dim3 grid(DOUT / 64, (n + 127) / 128);
        k_sgemm<64, 4, true, false><<<grid, 256>>>(h, W_out, b_out, out, nullptr, nullptr, n, DH, DOUT);
    }
}

// round 6
// speedup vs baseline: 2.6058x; 2.1219x over previous
#include <cuda_runtime.h>
#include <cuda_bf16.h>
#include <cstdint>
#include <math.h>

#define N_NODES 50000
#define E_MAX   800000
#define DIN     128
#define DH      256
#define DOUT    64
#define LAYERS  4

// ---------------- device scratch (allocation-free) ----------------
__device__ float g_dinv[N_NODES];
__device__ float g_norm[E_MAX];
__device__ float g_ht [(size_t)N_NODES * DH];
__device__ float g_agg[(size_t)N_NODES * DH];
__device__ __nv_bfloat16 g_xhi[(size_t)N_NODES * DIN];
__device__ __nv_bfloat16 g_xlo[(size_t)N_NODES * DIN];
__device__ __nv_bfloat16 g_hhi[(size_t)N_NODES * DH];
__device__ __nv_bfloat16 g_hlo[(size_t)N_NODES * DH];
// transposed bf16 weights [N][K] (K-major rows)
__device__ __nv_bfloat16 g_wembh[DH * DIN], g_wembl[DH * DIN];
__device__ __nv_bfloat16 g_wconvh[LAYERS * DH * DH], g_wconvl[LAYERS * DH * DH];
__device__ __nv_bfloat16 g_wouth[DOUT * DH], g_woutl[DOUT * DH];

// ---------------- degree / norm ----------------
__global__ void k_deg_init(float* deg, int n) {
    int i = blockIdx.x * blockDim.x + threadIdx.x;
    if (i < n) deg[i] = 1.0f;
}
__global__ void k_deg_accum(const int* __restrict__ dst, float* deg, int E) {
    int e = blockIdx.x * blockDim.x + threadIdx.x;
    if (e < E) atomicAdd(&deg[dst[e]], 1.0f);
}
__global__ void k_dinv(float* deg, int n) {
    int i = blockIdx.x * blockDim.x + threadIdx.x;
    if (i < n) { float d = deg[i]; deg[i] = (d > 0.f) ? rsqrtf(d) : 0.f; }
}
__global__ void k_norm(const int* __restrict__ src, const int* __restrict__ dst,
                       const float* __restrict__ dinv, float* __restrict__ norm, int E) {
    int e = blockIdx.x * blockDim.x + threadIdx.x;
    if (e < E) norm[e] = dinv[src[e]] * dinv[dst[e]];
}

// ---------------- conversions ----------------
__device__ __forceinline__ void split_bf16(float v, __nv_bfloat16& hi, __nv_bfloat16& lo) {
    hi = __float2bfloat16_rn(v);
    lo = __float2bfloat16_rn(v - __bfloat162float(hi));
}

__global__ void k_conv_x(const float* __restrict__ x,
                         __nv_bfloat16* __restrict__ hi, __nv_bfloat16* __restrict__ lo,
                         int total) {
    int i = blockIdx.x * blockDim.x + threadIdx.x;
    if (i >= total) return;
    split_bf16(x[i], hi[i], lo[i]);
}

// W [K][N] fp32 -> out [N][K] bf16 hi/lo
__global__ void k_conv_w(const float* __restrict__ W,
                         __nv_bfloat16* __restrict__ hi, __nv_bfloat16* __restrict__ lo,
                         int K, int N) {
    int i = blockIdx.x * blockDim.x + threadIdx.x;
    if (i >= K * N) return;
    int k = i / N, n = i % N;
    __nv_bfloat16 h, l;
    split_bf16(W[i], h, l);
    hi[(size_t)n * K + k] = h;
    lo[(size_t)n * K + k] = l;
}

// ---------------- mma.sync bf16 GEMM with 3-term compensation ----------------
// C[M,N] = (Ahi+Alo)[M,K] @ (Bhi+Blo)^T  (B stored [N][K] K-major)
// BM=128, BN=64, BK=32, 256 threads = 8 warps (4m x 2n), warp tile 32x32.
// EPI: 0 = bias + bf16 split out (emb), 1 = ht fp32 + agg = v*dinv^2 (conv),
//      2 = bias + fp32 out
__device__ __forceinline__ void mma16816(float* c, const uint32_t* a, const uint32_t* b) {
    asm volatile(
        "mma.sync.aligned.m16n8k16.row.col.f32.bf16.bf16.f32 "
        "{%0,%1,%2,%3}, {%4,%5,%6,%7}, {%8,%9}, {%0,%1,%2,%3};"
        : "+f"(c[0]), "+f"(c[1]), "+f"(c[2]), "+f"(c[3])
        : "r"(a[0]), "r"(a[1]), "r"(a[2]), "r"(a[3]), "r"(b[0]), "r"(b[1]));
}

template<int KTOT, int EPI>
__global__ __launch_bounds__(256)
void k_mma_gemm(const __nv_bfloat16* __restrict__ Ahi, const __nv_bfloat16* __restrict__ Alo,
                const __nv_bfloat16* __restrict__ Bhi, const __nv_bfloat16* __restrict__ Blo,
                const float* __restrict__ bias, const float* __restrict__ dinv,
                float* __restrict__ Cf, float* __restrict__ Cagg,
                __nv_bfloat16* __restrict__ Chi, __nv_bfloat16* __restrict__ Clo,
                int M, int Nout) {
    constexpr int BN = 64, BK = 32, LDS = 40;   // padded stride (80B, 16B-aligned)
    constexpr int NT = 4;                        // 4 n-tiles of 8 per warp
    __shared__ __nv_bfloat16 AsH[128][LDS], AsL[128][LDS];
    __shared__ __nv_bfloat16 BsH[BN][LDS],  BsL[BN][LDS];

    int tid = threadIdx.x;
    int lane = tid & 31, wid = tid >> 5;
    int wm = wid & 3, wn = wid >> 2;             // warp: rows wm*32, cols wn*32
    int g = lane >> 2, t2 = (lane & 3) * 2;

    int row0 = blockIdx.y * 128;
    int col0 = blockIdx.x * BN;

    float acc[2][NT][4];
    #pragma unroll
    for (int mt = 0; mt < 2; mt++)
        #pragma unroll
        for (int nt = 0; nt < NT; nt++)
            #pragma unroll
            for (int j = 0; j < 4; j++) acc[mt][nt][j] = 0.f;

    for (int kc = 0; kc < KTOT; kc += BK) {
        // A chunk: 128 rows x 32 bf16 (hi+lo). 512 uint4 per matrix.
        #pragma unroll
        for (int u = tid; u < 512; u += 256) {
            int row = u >> 2, q = u & 3;
            int gr = row0 + row;
            uint4 vh = make_uint4(0,0,0,0), vl = make_uint4(0,0,0,0);
            if (gr < M) {
                const __nv_bfloat16* p = Ahi + (size_t)gr * KTOT + kc;
                vh = *reinterpret_cast<const uint4*>(p + q * 8);
                const __nv_bfloat16* p2 = Alo + (size_t)gr * KTOT + kc;
                vl = *reinterpret_cast<const uint4*>(p2 + q * 8);
            }
            *reinterpret_cast<uint4*>(&AsH[row][q * 8]) = vh;
            *reinterpret_cast<uint4*>(&AsL[row][q * 8]) = vl;
        }
        // B chunk: BN rows x 32 bf16 (hi+lo). BN*4 uint4 per matrix.
        #pragma unroll
        for (int u = tid; u < BN * 4; u += 256) {
            int row = u >> 2, q = u & 3;
            int gn = col0 + row;
            *reinterpret_cast<uint4*>(&BsH[row][q * 8]) =
                *reinterpret_cast<const uint4*>(Bhi + (size_t)gn * KTOT + kc + q * 8);
            *reinterpret_cast<uint4*>(&BsL[row][q * 8]) =
                *reinterpret_cast<const uint4*>(Blo + (size_t)gn * KTOT + kc + q * 8);
        }
        __syncthreads();

        #pragma unroll
        for (int ko = 0; ko < BK; ko += 16) {
            uint32_t ah[2][4], al[2][4];
            #pragma unroll
            for (int mt = 0; mt < 2; mt++) {
                int rb = wm * 32 + mt * 16;
                ah[mt][0] = *reinterpret_cast<const uint32_t*>(&AsH[rb + g    ][ko + t2    ]);
                ah[mt][1] = *reinterpret_cast<const uint32_t*>(&AsH[rb + g + 8][ko + t2    ]);
                ah[mt][2] = *reinterpret_cast<const uint32_t*>(&AsH[rb + g    ][ko + t2 + 8]);
                ah[mt][3] = *reinterpret_cast<const uint32_t*>(&AsH[rb + g + 8][ko + t2 + 8]);
                al[mt][0] = *reinterpret_cast<const uint32_t*>(&AsL[rb + g    ][ko + t2    ]);
                al[mt][1] = *reinterpret_cast<const uint32_t*>(&AsL[rb + g + 8][ko + t2    ]);
                al[mt][2] = *reinterpret_cast<const uint32_t*>(&AsL[rb + g    ][ko + t2 + 8]);
                al[mt][3] = *reinterpret_cast<const uint32_t*>(&AsL[rb + g + 8][ko + t2 + 8]);
            }
            uint32_t bh[NT][2], bl[NT][2];
            #pragma unroll
            for (int nt = 0; nt < NT; nt++) {
                int nb = wn * 32 + nt * 8 + g;
                bh[nt][0] = *reinterpret_cast<const uint32_t*>(&BsH[nb][ko + t2    ]);
                bh[nt][1] = *reinterpret_cast<const uint32_t*>(&BsH[nb][ko + t2 + 8]);
                bl[nt][0] = *reinterpret_cast<const uint32_t*>(&BsL[nb][ko + t2    ]);
                bl[nt][1] = *reinterpret_cast<const uint32_t*>(&BsL[nb][ko + t2 + 8]);
            }
            #pragma unroll
            for (int mt = 0; mt < 2; mt++)
                #pragma unroll
                for (int nt = 0; nt < NT; nt++) {
                    mma16816(acc[mt][nt], ah[mt], bh[nt]);
                    mma16816(acc[mt][nt], ah[mt], bl[nt]);
                    mma16816(acc[mt][nt], al[mt], bh[nt]);
                }
        }
        __syncthreads();
    }

    // ---------------- epilogue ----------------
    #pragma unroll
    for (int mt = 0; mt < 2; mt++) {
        int rbase = row0 + wm * 32 + mt * 16;
        #pragma unroll
        for (int half = 0; half < 2; half++) {      // rows g and g+8
            int r = rbase + g + half * 8;
            if (r >= M) continue;
            float wdi = 0.f;
            if (EPI == 1) { float d0 = dinv[r]; wdi = d0 * d0; }
            #pragma unroll
            for (int nt = 0; nt < NT; nt++) {
                int c = col0 + wn * 32 + nt * 8 + t2;
                float v0 = acc[mt][nt][half * 2 + 0];
                float v1 = acc[mt][nt][half * 2 + 1];
                if (EPI != 1) { v0 += bias[c]; v1 += bias[c + 1]; }
                if (EPI == 0) {
                    __nv_bfloat16 h0, l0, h1, l1;
                    split_bf16(v0, h0, l0);
                    split_bf16(v1, h1, l1);
                    __nv_bfloat162 ph; ph.x = h0; ph.y = h1;
                    __nv_bfloat162 pl; pl.x = l0; pl.y = l1;
                    *reinterpret_cast<__nv_bfloat162*>(&Chi[(size_t)r * Nout + c]) = ph;
                    *reinterpret_cast<__nv_bfloat162*>(&Clo[(size_t)r * Nout + c]) = pl;
                } else if (EPI == 1) {
                    float2 hv = make_float2(v0, v1);
                    *reinterpret_cast<float2*>(&Cf[(size_t)r * Nout + c]) = hv;
                    float2 av = make_float2(v0 * wdi, v1 * wdi);
                    *reinterpret_cast<float2*>(&Cagg[(size_t)r * Nout + c]) = av;
                } else {
                    float2 ov = make_float2(v0, v1);
                    *reinterpret_cast<float2*>(&Cf[(size_t)r * Nout + c]) = ov;
                }
            }
        }
    }
}

// ---------------- aggregation ----------------
// 64 threads per edge, one float4 vector atomic each
__global__ void k_scatter(const int* __restrict__ src, const int* __restrict__ dst,
                          const float* __restrict__ norm,
                          const float* __restrict__ ht, float* __restrict__ agg, int E) {
    long long t = (long long)blockIdx.x * blockDim.x + threadIdx.x;
    int e = (int)(t >> 6);
    int lane = (int)(t & 63);
    if (e >= E) return;
    int s = src[e], d = dst[e];
    float w = norm[e];
    float4 v = reinterpret_cast<const float4*>(ht + (size_t)s * DH)[lane];
    float4 sv = make_float4(v.x * w, v.y * w, v.z * w, v.w * w);
    atomicAdd(reinterpret_cast<float4*>(agg + (size_t)d * DH + lane * 4), sv);
}

// h = tanh(agg + b) -> bf16 split
__global__ void k_finalize(const float* __restrict__ agg, const float* __restrict__ b,
                           __nv_bfloat16* __restrict__ hhi, __nv_bfloat16* __restrict__ hlo,
                           int n) {
    int t = blockIdx.x * blockDim.x + threadIdx.x;
    int total = n * DH;
    if (t >= total) return;
    int d = t & (DH - 1);
    float v = tanhf(agg[t] + b[d]);
    split_bf16(v, hhi[t], hlo[t]);
}

// ---------------- launcher ----------------
extern "C" void kernel_launch(void* const* d_in, const int* in_sizes, int n_in,
                              void* d_out, int out_size) {
    const float* x      = (const float*)d_in[0];
    const int*   eidx   = (const int*)  d_in[1];
    const float* W_emb  = (const float*)d_in[2];
    const float* b_emb  = (const float*)d_in[3];
    const float* W_conv = (const float*)d_in[4];
    const float* b_conv = (const float*)d_in[5];
    const float* W_out  = (const float*)d_in[6];
    const float* b_out  = (const float*)d_in[7];
    float* out = (float*)d_out;

    int E = in_sizes[1] / 2;
    if (E > E_MAX) E = E_MAX;
    const int* src = eidx;
    const int* dst = eidx + E;
    const int n = N_NODES;

    float *dinv, *norm, *ht, *agg;
    __nv_bfloat16 *xhi, *xlo, *hhi, *hlo;
    __nv_bfloat16 *wembh, *wembl, *wconvh, *wconvl, *wouth, *woutl;
    cudaGetSymbolAddress((void**)&dinv, g_dinv);
    cudaGetSymbolAddress((void**)&norm, g_norm);
    cudaGetSymbolAddress((void**)&ht,   g_ht);
    cudaGetSymbolAddress((void**)&agg,  g_agg);
    cudaGetSymbolAddress((void**)&xhi,  g_xhi);
    cudaGetSymbolAddress((void**)&xlo,  g_xlo);
    cudaGetSymbolAddress((void**)&hhi,  g_hhi);
    cudaGetSymbolAddress((void**)&hlo,  g_hlo);
    cudaGetSymbolAddress((void**)&wembh, g_wembh);
    cudaGetSymbolAddress((void**)&wembl, g_wembl);
    cudaGetSymbolAddress((void**)&wconvh, g_wconvh);
    cudaGetSymbolAddress((void**)&wconvl, g_wconvl);
    cudaGetSymbolAddress((void**)&wouth, g_wouth);
    cudaGetSymbolAddress((void**)&woutl, g_woutl);

    // degree / norm
    k_deg_init <<<(n + 255) / 256, 256>>>(dinv, n);
    k_deg_accum<<<(E + 255) / 256, 256>>>(dst, dinv, E);
    k_dinv     <<<(n + 255) / 256, 256>>>(dinv, n);
    k_norm     <<<(E + 255) / 256, 256>>>(src, dst, dinv, norm, E);

    // conversions
    k_conv_x<<<(n * DIN + 255) / 256, 256>>>(x, xhi, xlo, n * DIN);
    k_conv_w<<<(DIN * DH + 255) / 256, 256>>>(W_emb, wembh, wembl, DIN, DH);
    for (int l = 0; l < LAYERS; l++)
        k_conv_w<<<(DH * DH + 255) / 256, 256>>>(W_conv + (size_t)l * DH * DH,
                                                 wconvh + (size_t)l * DH * DH,
                                                 wconvl + (size_t)l * DH * DH, DH, DH);
    k_conv_w<<<(DH * DOUT + 255) / 256, 256>>>(W_out, wouth, woutl, DH, DOUT);

    int gy = (n + 127) / 128;   // 391

    // embedding: h = x @ W_emb + b_emb -> bf16 split
    {
        dim3 grid(DH / 64, gy);
        k_mma_gemm<DIN, 0><<<grid, 256>>>(xhi, xlo, wembh, wembl, b_emb, nullptr,
                                          nullptr, nullptr, hhi, hlo, n, DH);
    }

    long long scat_threads = (long long)E * 64;
    int scat_blocks = (int)((scat_threads + 255) / 256);
    for (int l = 0; l < LAYERS; l++) {
        const float* b = b_conv + (size_t)l * DH;
        dim3 grid(DH / 64, gy);
        k_mma_gemm<DH, 1><<<grid, 256>>>(hhi, hlo,
                                         wconvh + (size_t)l * DH * DH,
                                         wconvl + (size_t)l * DH * DH,
                                         nullptr, dinv, ht, agg, nullptr, nullptr, n, DH);
        k_scatter<<<scat_blocks, 256>>>(src, dst, norm, ht, agg, E);
        k_finalize<<<(n * DH + 255) / 256, 256>>>(agg, b, hhi, hlo, n);
    }

    // output: out = h @ W_out + b_out
    {
        dim3 grid(DOUT / 64, gy);
        k_mma_gemm<DH, 2><<<grid, 256>>>(hhi, hlo, wouth, woutl, b_out, nullptr,
                                         out, nullptr, nullptr, nullptr, n, DOUT);
    }
}

// round 9
// speedup vs baseline: 4.3753x; 1.6790x over previous
#include <cuda_runtime.h>
#include <cuda_bf16.h>
#include <cstdint>
#include <math.h>

#define N_NODES 50000
#define E_MAX   800000
#define DIN     128
#define DH      256
#define DOUT    64
#define LAYERS  4

// ---------------- device scratch (allocation-free) ----------------
__device__ float g_dinv[N_NODES];
__device__ int   g_cnt[N_NODES];
__device__ int   g_rowptr[N_NODES + 1];
__device__ int   g_cursor[N_NODES];
__device__ int2  g_csr[E_MAX];                    // {src, norm-as-int}
__device__ float g_ht [(size_t)N_NODES * DH];
__device__ __nv_bfloat16 g_xhi[(size_t)N_NODES * DIN];
__device__ __nv_bfloat16 g_xlo[(size_t)N_NODES * DIN];
__device__ __nv_bfloat16 g_hhi[(size_t)N_NODES * DH];
__device__ __nv_bfloat16 g_hlo[(size_t)N_NODES * DH];
// transposed bf16 weights [N][K] (K-major rows)
__device__ __nv_bfloat16 g_wembh[DH * DIN], g_wembl[DH * DIN];
__device__ __nv_bfloat16 g_wconvh[LAYERS * DH * DH], g_wconvl[LAYERS * DH * DH];
__device__ __nv_bfloat16 g_wouth[DOUT * DH], g_woutl[DOUT * DH];

// ---------------- CSR build ----------------
__global__ void k_zero(int* cnt, int n) {
    int i = blockIdx.x * blockDim.x + threadIdx.x;
    if (i < n) cnt[i] = 0;
}
__global__ void k_count(const int* __restrict__ dst, int* cnt, int E) {
    int e = blockIdx.x * blockDim.x + threadIdx.x;
    if (e < E) atomicAdd(&cnt[dst[e]], 1);
}
__global__ void k_dinv(const int* __restrict__ cnt, float* dinv, int n) {
    int i = blockIdx.x * blockDim.x + threadIdx.x;
    if (i < n) dinv[i] = rsqrtf((float)cnt[i] + 1.0f);   // +1 self-loop
}
// single-block exclusive scan of cnt -> rowptr, cursor
__global__ void k_scan(const int* __restrict__ cnt, int* rowptr, int* cursor, int n) {
    __shared__ int ssum[1024];
    int t = threadIdx.x;
    const int CH = (n + 1023) / 1024;
    int start = t * CH;
    int s = 0;
    for (int i = 0; i < CH; i++) {
        int idx = start + i;
        if (idx < n) s += cnt[idx];
    }
    ssum[t] = s;
    __syncthreads();
    for (int off = 1; off < 1024; off <<= 1) {
        int tmp = (t >= off) ? ssum[t - off] : 0;
        __syncthreads();
        ssum[t] += tmp;
        __syncthreads();
    }
    int run = ssum[t] - s;                        // exclusive base
    for (int i = 0; i < CH; i++) {
        int idx = start + i;
        if (idx < n) {
            rowptr[idx] = run;
            cursor[idx] = run;
            run += cnt[idx];
        }
    }
    if (t == 1023) rowptr[n] = ssum[1023];
}
__global__ void k_fill(const int* __restrict__ src, const int* __restrict__ dst,
                       const float* __restrict__ dinv, int* cursor,
                       int2* __restrict__ csr, int E) {
    int e = blockIdx.x * blockDim.x + threadIdx.x;
    if (e >= E) return;
    int s = src[e], d = dst[e];
    int pos = atomicAdd(&cursor[d], 1);
    float w = dinv[s] * dinv[d];
    csr[pos] = make_int2(s, __float_as_int(w));
}

// ---------------- conversions ----------------
__device__ __forceinline__ void split_bf16(float v, __nv_bfloat16& hi, __nv_bfloat16& lo) {
    hi = __float2bfloat16_rn(v);
    lo = __float2bfloat16_rn(v - __bfloat162float(hi));
}

__global__ void k_conv_x(const float* __restrict__ x,
                         __nv_bfloat16* __restrict__ hi, __nv_bfloat16* __restrict__ lo,
                         int total) {
    int i = blockIdx.x * blockDim.x + threadIdx.x;
    if (i >= total) return;
    split_bf16(x[i], hi[i], lo[i]);
}

// W [K][N] fp32 -> out [N][K] bf16 hi/lo
__global__ void k_conv_w(const float* __restrict__ W,
                         __nv_bfloat16* __restrict__ hi, __nv_bfloat16* __restrict__ lo,
                         int K, int N) {
    int i = blockIdx.x * blockDim.x + threadIdx.x;
    if (i >= K * N) return;
    int k = i / N, n = i % N;
    __nv_bfloat16 h, l;
    split_bf16(W[i], h, l);
    hi[(size_t)n * K + k] = h;
    lo[(size_t)n * K + k] = l;
}

// ---------------- mma.sync bf16 GEMM with 3-term compensation ----------------
// C[M,N] = (Ahi+Alo)[M,K] @ (Bhi+Blo)^T  (B stored [N][K] K-major)
// BM=128, BN=64, BK=32, 256 threads = 8 warps (4m x 2n), warp tile 32x32.
// EPI: 0 = bias + bf16 split out (emb), 1 = plain fp32 write (conv), 2 = bias + fp32 (out)
__device__ __forceinline__ void mma16816(float* c, const uint32_t* a, const uint32_t* b) {
    asm volatile(
        "mma.sync.aligned.m16n8k16.row.col.f32.bf16.bf16.f32 "
        "{%0,%1,%2,%3}, {%4,%5,%6,%7}, {%8,%9}, {%0,%1,%2,%3};"
        : "+f"(c[0]), "+f"(c[1]), "+f"(c[2]), "+f"(c[3])
        : "r"(a[0]), "r"(a[1]), "r"(a[2]), "r"(a[3]), "r"(b[0]), "r"(b[1]));
}

template<int KTOT, int EPI>
__global__ __launch_bounds__(256)
void k_mma_gemm(const __nv_bfloat16* __restrict__ Ahi, const __nv_bfloat16* __restrict__ Alo,
                const __nv_bfloat16* __restrict__ Bhi, const __nv_bfloat16* __restrict__ Blo,
                const float* __restrict__ bias,
                float* __restrict__ Cf,
                __nv_bfloat16* __restrict__ Chi, __nv_bfloat16* __restrict__ Clo,
                int M, int Nout) {
    constexpr int BN = 64, BK = 32, LDS = 40;
    constexpr int NT = 4;
    __shared__ __nv_bfloat16 AsH[128][LDS], AsL[128][LDS];
    __shared__ __nv_bfloat16 BsH[BN][LDS],  BsL[BN][LDS];

    int tid = threadIdx.x;
    int lane = tid & 31, wid = tid >> 5;
    int wm = wid & 3, wn = wid >> 2;
    int g = lane >> 2, t2 = (lane & 3) * 2;

    int row0 = blockIdx.y * 128;
    int col0 = blockIdx.x * BN;

    float acc[2][NT][4];
    #pragma unroll
    for (int mt = 0; mt < 2; mt++)
        #pragma unroll
        for (int nt = 0; nt < NT; nt++)
            #pragma unroll
            for (int j = 0; j < 4; j++) acc[mt][nt][j] = 0.f;

    for (int kc = 0; kc < KTOT; kc += BK) {
        #pragma unroll
        for (int u = tid; u < 512; u += 256) {
            int row = u >> 2, q = u & 3;
            int gr = row0 + row;
            uint4 vh = make_uint4(0,0,0,0), vl = make_uint4(0,0,0,0);
            if (gr < M) {
                vh = *reinterpret_cast<const uint4*>(Ahi + (size_t)gr * KTOT + kc + q * 8);
                vl = *reinterpret_cast<const uint4*>(Alo + (size_t)gr * KTOT + kc + q * 8);
            }
            *reinterpret_cast<uint4*>(&AsH[row][q * 8]) = vh;
            *reinterpret_cast<uint4*>(&AsL[row][q * 8]) = vl;
        }
        #pragma unroll
        for (int u = tid; u < BN * 4; u += 256) {
            int row = u >> 2, q = u & 3;
            int gn = col0 + row;
            *reinterpret_cast<uint4*>(&BsH[row][q * 8]) =
                *reinterpret_cast<const uint4*>(Bhi + (size_t)gn * KTOT + kc + q * 8);
            *reinterpret_cast<uint4*>(&BsL[row][q * 8]) =
                *reinterpret_cast<const uint4*>(Blo + (size_t)gn * KTOT + kc + q * 8);
        }
        __syncthreads();

        #pragma unroll
        for (int ko = 0; ko < BK; ko += 16) {
            uint32_t ah[2][4], al[2][4];
            #pragma unroll
            for (int mt = 0; mt < 2; mt++) {
                int rb = wm * 32 + mt * 16;
                ah[mt][0] = *reinterpret_cast<const uint32_t*>(&AsH[rb + g    ][ko + t2    ]);
                ah[mt][1] = *reinterpret_cast<const uint32_t*>(&AsH[rb + g + 8][ko + t2    ]);
                ah[mt][2] = *reinterpret_cast<const uint32_t*>(&AsH[rb + g    ][ko + t2 + 8]);
                ah[mt][3] = *reinterpret_cast<const uint32_t*>(&AsH[rb + g + 8][ko + t2 + 8]);
                al[mt][0] = *reinterpret_cast<const uint32_t*>(&AsL[rb + g    ][ko + t2    ]);
                al[mt][1] = *reinterpret_cast<const uint32_t*>(&AsL[rb + g + 8][ko + t2    ]);
                al[mt][2] = *reinterpret_cast<const uint32_t*>(&AsL[rb + g    ][ko + t2 + 8]);
                al[mt][3] = *reinterpret_cast<const uint32_t*>(&AsL[rb + g + 8][ko + t2 + 8]);
            }
            uint32_t bh[NT][2], bl[NT][2];
            #pragma unroll
            for (int nt = 0; nt < NT; nt++) {
                int nb = wn * 32 + nt * 8 + g;
                bh[nt][0] = *reinterpret_cast<const uint32_t*>(&BsH[nb][ko + t2    ]);
                bh[nt][1] = *reinterpret_cast<const uint32_t*>(&BsH[nb][ko + t2 + 8]);
                bl[nt][0] = *reinterpret_cast<const uint32_t*>(&BsL[nb][ko + t2    ]);
                bl[nt][1] = *reinterpret_cast<const uint32_t*>(&BsL[nb][ko + t2 + 8]);
            }
            #pragma unroll
            for (int mt = 0; mt < 2; mt++)
                #pragma unroll
                for (int nt = 0; nt < NT; nt++) {
                    mma16816(acc[mt][nt], ah[mt], bh[nt]);
                    mma16816(acc[mt][nt], ah[mt], bl[nt]);
                    mma16816(acc[mt][nt], al[mt], bh[nt]);
                }
        }
        __syncthreads();
    }

    #pragma unroll
    for (int mt = 0; mt < 2; mt++) {
        int rbase = row0 + wm * 32 + mt * 16;
        #pragma unroll
        for (int half = 0; half < 2; half++) {
            int r = rbase + g + half * 8;
            if (r >= M) continue;
            #pragma unroll
            for (int nt = 0; nt < NT; nt++) {
                int c = col0 + wn * 32 + nt * 8 + t2;
                float v0 = acc[mt][nt][half * 2 + 0];
                float v1 = acc[mt][nt][half * 2 + 1];
                if (EPI != 1) { v0 += bias[c]; v1 += bias[c + 1]; }
                if (EPI == 0) {
                    __nv_bfloat16 h0, l0, h1, l1;
                    split_bf16(v0, h0, l0);
                    split_bf16(v1, h1, l1);
                    __nv_bfloat162 ph; ph.x = h0; ph.y = h1;
                    __nv_bfloat162 pl; pl.x = l0; pl.y = l1;
                    *reinterpret_cast<__nv_bfloat162*>(&Chi[(size_t)r * Nout + c]) = ph;
                    *reinterpret_cast<__nv_bfloat162*>(&Clo[(size_t)r * Nout + c]) = pl;
                } else {
                    *reinterpret_cast<float2*>(&Cf[(size_t)r * Nout + c]) = make_float2(v0, v1);
                }
            }
        }
    }
}

// ---------------- fused gather aggregation ----------------
// One warp per dst node: acc = ht[i]*dinv[i]^2 + sum ht[src]*norm;
// h = tanh(acc + b) -> bf16 split. Lane owns 8 contiguous floats.
__global__ __launch_bounds__(256)
void k_gather(const float* __restrict__ ht, const int2* __restrict__ csr,
              const int* __restrict__ rowptr, const float* __restrict__ dinv,
              const float* __restrict__ b,
              __nv_bfloat16* __restrict__ hhi, __nv_bfloat16* __restrict__ hlo, int n) {
    int warp = (blockIdx.x * blockDim.x + threadIdx.x) >> 5;
    int lane = threadIdx.x & 31;
    if (warp >= n) return;
    int i = warp;

    float di = dinv[i];
    float w0 = di * di;
    const float4* row = reinterpret_cast<const float4*>(ht + (size_t)i * DH);
    float4 a0 = row[lane * 2], a1 = row[lane * 2 + 1];
    float acc[8] = { a0.x * w0, a0.y * w0, a0.z * w0, a0.w * w0,
                     a1.x * w0, a1.y * w0, a1.z * w0, a1.w * w0 };

    int beg = rowptr[i], end = rowptr[i + 1];
    int j = beg;
    for (; j + 1 < end; j += 2) {
        int2 e0 = csr[j], e1 = csr[j + 1];
        const float4* r0 = reinterpret_cast<const float4*>(ht + (size_t)e0.x * DH);
        const float4* r1 = reinterpret_cast<const float4*>(ht + (size_t)e1.x * DH);
        float wa = __int_as_float(e0.y), wb = __int_as_float(e1.y);
        float4 v0 = r0[lane * 2], v1 = r0[lane * 2 + 1];
        float4 u0 = r1[lane * 2], u1 = r1[lane * 2 + 1];
        acc[0] += v0.x * wa; acc[1] += v0.y * wa; acc[2] += v0.z * wa; acc[3] += v0.w * wa;
        acc[4] += v1.x * wa; acc[5] += v1.y * wa; acc[6] += v1.z * wa; acc[7] += v1.w * wa;
        acc[0] += u0.x * wb; acc[1] += u0.y * wb; acc[2] += u0.z * wb; acc[3] += u0.w * wb;
        acc[4] += u1.x * wb; acc[5] += u1.y * wb; acc[6] += u1.z * wb; acc[7] += u1.w * wb;
    }
    if (j < end) {
        int2 e0 = csr[j];
        const float4* r0 = reinterpret_cast<const float4*>(ht + (size_t)e0.x * DH);
        float wa = __int_as_float(e0.y);
        float4 v0 = r0[lane * 2], v1 = r0[lane * 2 + 1];
        acc[0] += v0.x * wa; acc[1] += v0.y * wa; acc[2] += v0.z * wa; acc[3] += v0.w * wa;
        acc[4] += v1.x * wa; acc[5] += v1.y * wa; acc[6] += v1.z * wa; acc[7] += v1.w * wa;
    }

    const float4* bp = reinterpret_cast<const float4*>(b);
    float4 b0 = bp[lane * 2], b1 = bp[lane * 2 + 1];
    float bb[8] = { b0.x, b0.y, b0.z, b0.w, b1.x, b1.y, b1.z, b1.w };

    __nv_bfloat16 hh[8], ll[8];
    #pragma unroll
    for (int q = 0; q < 8; q++) {
        float v = tanhf(acc[q] + bb[q]);
        split_bf16(v, hh[q], ll[q]);
    }
    *reinterpret_cast<uint4*>(hhi + (size_t)i * DH + lane * 8) = *reinterpret_cast<uint4*>(hh);
    *reinterpret_cast<uint4*>(hlo + (size_t)i * DH + lane * 8) = *reinterpret_cast<uint4*>(ll);
}

// ---------------- launcher ----------------
extern "C" void kernel_launch(void* const* d_in, const int* in_sizes, int n_in,
                              void* d_out, int out_size) {
    const float* x      = (const float*)d_in[0];
    const int*   eidx   = (const int*)  d_in[1];
    const float* W_emb  = (const float*)d_in[2];
    const float* b_emb  = (const float*)d_in[3];
    const float* W_conv = (const float*)d_in[4];
    const float* b_conv = (const float*)d_in[5];
    const float* W_out  = (const float*)d_in[6];
    const float* b_out  = (const float*)d_in[7];
    float* out = (float*)d_out;

    int E = in_sizes[1] / 2;
    if (E > E_MAX) E = E_MAX;
    const int* src = eidx;
    const int* dst = eidx + E;
    const int n = N_NODES;

    float *dinv, *ht;
    int *cnt, *rowptr, *cursor;
    int2 *csr;
    __nv_bfloat16 *xhi, *xlo, *hhi, *hlo;
    __nv_bfloat16 *wembh, *wembl, *wconvh, *wconvl, *wouth, *woutl;
    cudaGetSymbolAddress((void**)&dinv, g_dinv);
    cudaGetSymbolAddress((void**)&cnt,    g_cnt);
    cudaGetSymbolAddress((void**)&rowptr, g_rowptr);
    cudaGetSymbolAddress((void**)&cursor, g_cursor);
    cudaGetSymbolAddress((void**)&csr,    g_csr);
    cudaGetSymbolAddress((void**)&ht,   g_ht);
    cudaGetSymbolAddress((void**)&xhi,  g_xhi);
    cudaGetSymbolAddress((void**)&xlo,  g_xlo);
    cudaGetSymbolAddress((void**)&hhi,  g_hhi);
    cudaGetSymbolAddress((void**)&hlo,  g_hlo);
    cudaGetSymbolAddress((void**)&wembh, g_wembh);
    cudaGetSymbolAddress((void**)&wembl, g_wembl);
    cudaGetSymbolAddress((void**)&wconvh, g_wconvh);
    cudaGetSymbolAddress((void**)&wconvl, g_wconvl);
    cudaGetSymbolAddress((void**)&wouth, g_wouth);
    cudaGetSymbolAddress((void**)&woutl, g_woutl);

    // CSR build + dinv
    k_zero <<<(n + 255) / 256, 256>>>(cnt, n);
    k_count<<<(E + 255) / 256, 256>>>(dst, cnt, E);
    k_dinv <<<(n + 255) / 256, 256>>>(cnt, dinv, n);
    k_scan <<<1, 1024>>>(cnt, rowptr, cursor, n);
    k_fill <<<(E + 255) / 256, 256>>>(src, dst, dinv, cursor, csr, E);

    // conversions
    k_conv_x<<<(n * DIN + 255) / 256, 256>>>(x, xhi, xlo, n * DIN);
    k_conv_w<<<(DIN * DH + 255) / 256, 256>>>(W_emb, wembh, wembl, DIN, DH);
    for (int l = 0; l < LAYERS; l++)
        k_conv_w<<<(DH * DH + 255) / 256, 256>>>(W_conv + (size_t)l * DH * DH,
                                                 wconvh + (size_t)l * DH * DH,
                                                 wconvl + (size_t)l * DH * DH, DH, DH);
    k_conv_w<<<(DH * DOUT + 255) / 256, 256>>>(W_out, wouth, woutl, DH, DOUT);

    int gy = (n + 127) / 128;

    // embedding: h = x @ W_emb + b_emb -> bf16 split
    {
        dim3 grid(DH / 64, gy);
        k_mma_gemm<DIN, 0><<<grid, 256>>>(xhi, xlo, wembh, wembl, b_emb,
                                          nullptr, hhi, hlo, n, DH);
    }

    int gather_blocks = (n * 32 + 255) / 256;
    for (int l = 0; l < LAYERS; l++) {
        const float* b = b_conv + (size_t)l * DH;
        dim3 grid(DH / 64, gy);
        k_mma_gemm<DH, 1><<<grid, 256>>>(hhi, hlo,
                                         wconvh + (size_t)l * DH * DH,
                                         wconvl + (size_t)l * DH * DH,
                                         nullptr, ht, nullptr, nullptr, n, DH);
        k_gather<<<gather_blocks, 256>>>(ht, csr, rowptr, dinv, b, hhi, hlo, n);
    }

    // output: out = h @ W_out + b_out
    {
        dim3 grid(DOUT / 64, gy);
        k_mma_gemm<DH, 2><<<grid, 256>>>(hhi, hlo, wouth, woutl, b_out,
                                         out, nullptr, nullptr, n, DOUT);
    }
}

// round 10
// speedup vs baseline: 5.1967x; 1.1877x over previous
#include <cuda_runtime.h>
#include <cuda_bf16.h>
#include <cstdint>
#include <math.h>

#define N_NODES 50000
#define E_MAX   800000
#define DIN     128
#define DH      256
#define DOUT    64
#define LAYERS  4

#define SCAN_NB  ((N_NODES + 1023) / 1024)   // 49

// ---------------- device scratch (allocation-free) ----------------
__device__ float g_dinv[N_NODES];
__device__ int   g_cnt[N_NODES];
__device__ int   g_partial[64];
__device__ int   g_rowptr[N_NODES + 1];
__device__ int   g_cursor[N_NODES];
__device__ int2  g_csr[E_MAX];                    // {src, norm-as-int}
__device__ float g_ht [(size_t)N_NODES * DH];
__device__ __nv_bfloat16 g_xhi[(size_t)N_NODES * DIN];
__device__ __nv_bfloat16 g_xlo[(size_t)N_NODES * DIN];
__device__ __nv_bfloat16 g_hhi[(size_t)N_NODES * DH];
__device__ __nv_bfloat16 g_hlo[(size_t)N_NODES * DH];
// transposed bf16 weights [N][K] (K-major rows)
__device__ __nv_bfloat16 g_wembh[DH * DIN], g_wembl[DH * DIN];
__device__ __nv_bfloat16 g_wconvh[LAYERS * DH * DH], g_wconvl[LAYERS * DH * DH];
__device__ __nv_bfloat16 g_wouth[DOUT * DH], g_woutl[DOUT * DH];

// ---------------- CSR build ----------------
__global__ void k_zero(int* cnt, int n) {
    int i = blockIdx.x * blockDim.x + threadIdx.x;
    if (i < n) cnt[i] = 0;
}
__global__ void k_count(const int* __restrict__ dst, int* cnt, int E) {
    int e = blockIdx.x * blockDim.x + threadIdx.x;
    if (e < E) atomicAdd(&cnt[dst[e]], 1);
}
__global__ void k_dinv(const int* __restrict__ cnt, float* dinv, int n) {
    int i = blockIdx.x * blockDim.x + threadIdx.x;
    if (i < n) dinv[i] = rsqrtf((float)cnt[i] + 1.0f);   // +1 self-loop
}

// scan stage 1: per-block (1024 elements) sum, coalesced
__global__ void k_scan1(const int* __restrict__ cnt, int* partial, int n) {
    __shared__ int sd[256];
    int base = blockIdx.x * 1024;
    int t = threadIdx.x;
    int s = 0;
    #pragma unroll
    for (int i = 0; i < 4; i++) {
        int idx = base + t + i * 256;
        if (idx < n) s += cnt[idx];
    }
    sd[t] = s;
    __syncthreads();
    #pragma unroll
    for (int off = 128; off > 0; off >>= 1) {
        if (t < off) sd[t] += sd[t + off];
        __syncthreads();
    }
    if (t == 0) partial[blockIdx.x] = sd[0];
}
// scan stage 2: exclusive scan of <=64 partials
__global__ void k_scan2(int* partial, int* rowptr, int nb, int n) {
    __shared__ int sh[64];
    int t = threadIdx.x;
    int v = (t < nb) ? partial[t] : 0;
    sh[t] = v;
    __syncthreads();
    #pragma unroll
    for (int off = 1; off < 64; off <<= 1) {
        int x = (t >= off) ? sh[t - off] : 0;
        __syncthreads();
        sh[t] += x;
        __syncthreads();
    }
    if (t < nb) partial[t] = sh[t] - v;      // exclusive
    if (t == 63) rowptr[n] = sh[63];
}
// scan stage 3: per-block exclusive scan + offset, fill rowptr & cursor
__global__ void k_scan3(const int* __restrict__ cnt, const int* __restrict__ partial,
                        int* rowptr, int* cursor, int n) {
    __shared__ int sh[256];
    int base = blockIdx.x * 1024;
    int t = threadIdx.x;
    int i0 = base + t * 4;
    int c0 = (i0     < n) ? cnt[i0    ] : 0;
    int c1 = (i0 + 1 < n) ? cnt[i0 + 1] : 0;
    int c2 = (i0 + 2 < n) ? cnt[i0 + 2] : 0;
    int c3 = (i0 + 3 < n) ? cnt[i0 + 3] : 0;
    int tot = c0 + c1 + c2 + c3;
    sh[t] = tot;
    __syncthreads();
    #pragma unroll
    for (int off = 1; off < 256; off <<= 1) {
        int x = (t >= off) ? sh[t - off] : 0;
        __syncthreads();
        sh[t] += x;
        __syncthreads();
    }
    int run = sh[t] - tot + partial[blockIdx.x];
    if (i0     < n) { rowptr[i0    ] = run; cursor[i0    ] = run; run += c0; }
    if (i0 + 1 < n) { rowptr[i0 + 1] = run; cursor[i0 + 1] = run; run += c1; }
    if (i0 + 2 < n) { rowptr[i0 + 2] = run; cursor[i0 + 2] = run; run += c2; }
    if (i0 + 3 < n) { rowptr[i0 + 3] = run; cursor[i0 + 3] = run; }
}

__global__ void k_fill(const int* __restrict__ src, const int* __restrict__ dst,
                       const float* __restrict__ dinv, int* cursor,
                       int2* __restrict__ csr, int E) {
    int e = blockIdx.x * blockDim.x + threadIdx.x;
    if (e >= E) return;
    int s = src[e], d = dst[e];
    int pos = atomicAdd(&cursor[d], 1);
    float w = dinv[s] * dinv[d];
    csr[pos] = make_int2(s, __float_as_int(w));
}

// ---------------- conversions ----------------
__device__ __forceinline__ void split_bf16(float v, __nv_bfloat16& hi, __nv_bfloat16& lo) {
    hi = __float2bfloat16_rn(v);
    lo = __float2bfloat16_rn(v - __bfloat162float(hi));
}

__global__ void k_conv_x(const float* __restrict__ x,
                         __nv_bfloat16* __restrict__ hi, __nv_bfloat16* __restrict__ lo,
                         int total) {
    int i = blockIdx.x * blockDim.x + threadIdx.x;
    if (i >= total) return;
    split_bf16(x[i], hi[i], lo[i]);
}

// W [K][N] fp32 -> out [N][K] bf16 hi/lo
__global__ void k_conv_w(const float* __restrict__ W,
                         __nv_bfloat16* __restrict__ hi, __nv_bfloat16* __restrict__ lo,
                         int K, int N) {
    int i = blockIdx.x * blockDim.x + threadIdx.x;
    if (i >= K * N) return;
    int k = i / N, n = i % N;
    __nv_bfloat16 h, l;
    split_bf16(W[i], h, l);
    hi[(size_t)n * K + k] = h;
    lo[(size_t)n * K + k] = l;
}

// ---------------- mma.sync bf16 GEMM, 3-term compensated, cp.async 2-stage ----------------
__device__ __forceinline__ void mma16816(float* c, const uint32_t* a, const uint32_t* b) {
    asm volatile(
        "mma.sync.aligned.m16n8k16.row.col.f32.bf16.bf16.f32 "
        "{%0,%1,%2,%3}, {%4,%5,%6,%7}, {%8,%9}, {%0,%1,%2,%3};"
        : "+f"(c[0]), "+f"(c[1]), "+f"(c[2]), "+f"(c[3])
        : "r"(a[0]), "r"(a[1]), "r"(a[2]), "r"(a[3]), "r"(b[0]), "r"(b[1]));
}
__device__ __forceinline__ void cp16(uint32_t dst, const void* src, bool valid) {
    int sz = valid ? 16 : 0;
    asm volatile("cp.async.cg.shared.global [%0], [%1], 16, %2;"
                 :: "r"(dst), "l"(src), "r"(sz) : "memory");
}

// smem layout per stage (elements): AsH[128*40] AsL[128*40] BsH[64*40] BsL[64*40]
#define LDSW  40
#define ST_AH 0
#define ST_AL (128 * LDSW)
#define ST_BH (2 * 128 * LDSW)
#define ST_BL (2 * 128 * LDSW + 64 * LDSW)
#define STAGE (2 * 128 * LDSW + 2 * 64 * LDSW)   // 15360 elements

template<int KTOT, int EPI>
__global__ __launch_bounds__(256)
void k_mma_gemm(const __nv_bfloat16* __restrict__ Ahi, const __nv_bfloat16* __restrict__ Alo,
                const __nv_bfloat16* __restrict__ Bhi, const __nv_bfloat16* __restrict__ Blo,
                const float* __restrict__ bias,
                float* __restrict__ Cf,
                __nv_bfloat16* __restrict__ Chi, __nv_bfloat16* __restrict__ Clo,
                int M, int Nout) {
    constexpr int BK = 32, NT = 4;
    constexpr int NCH = KTOT / BK;
    extern __shared__ __nv_bfloat16 smem[];

    int tid = threadIdx.x;
    int lane = tid & 31, wid = tid >> 5;
    int wm = wid & 3, wn = wid >> 2;
    int g = lane >> 2, t2 = (lane & 3) * 2;

    int row0 = blockIdx.y * 128;
    int col0 = blockIdx.x * 64;

    float acc[2][NT][4];
    #pragma unroll
    for (int mt = 0; mt < 2; mt++)
        #pragma unroll
        for (int nt = 0; nt < NT; nt++)
            #pragma unroll
            for (int j = 0; j < 4; j++) acc[mt][nt][j] = 0.f;

    // async load of chunk kc into stage s
    auto issue = [&](int c, int s) {
        int kc = c * BK;
        __nv_bfloat16* base = smem + s * STAGE;
        #pragma unroll
        for (int u = tid; u < 512; u += 256) {
            int row = u >> 2, q = u & 3;
            int gr = row0 + row;
            bool ok = gr < M;
            const __nv_bfloat16* pH = ok ? (Ahi + (size_t)gr * KTOT + kc + q * 8) : Ahi;
            const __nv_bfloat16* pL = ok ? (Alo + (size_t)gr * KTOT + kc + q * 8) : Alo;
            cp16((uint32_t)__cvta_generic_to_shared(base + ST_AH + row * LDSW + q * 8), pH, ok);
            cp16((uint32_t)__cvta_generic_to_shared(base + ST_AL + row * LDSW + q * 8), pL, ok);
        }
        {
            int u = tid;
            if (u < 256) {
                int row = u >> 2, q = u & 3;
                int gn = col0 + row;
                cp16((uint32_t)__cvta_generic_to_shared(base + ST_BH + row * LDSW + q * 8),
                     Bhi + (size_t)gn * KTOT + kc + q * 8, true);
                cp16((uint32_t)__cvta_generic_to_shared(base + ST_BL + row * LDSW + q * 8),
                     Blo + (size_t)gn * KTOT + kc + q * 8, true);
            }
        }
        asm volatile("cp.async.commit_group;" ::: "memory");
    };

    issue(0, 0);

    for (int c = 0; c < NCH; c++) {
        int s = c & 1;
        if (c + 1 < NCH) {
            issue(c + 1, (c + 1) & 1);
            asm volatile("cp.async.wait_group 1;" ::: "memory");
        } else {
            asm volatile("cp.async.wait_group 0;" ::: "memory");
        }
        __syncthreads();

        const __nv_bfloat16* base = smem + s * STAGE;
        const __nv_bfloat16* asH = base + ST_AH;
        const __nv_bfloat16* asL = base + ST_AL;
        const __nv_bfloat16* bsH = base + ST_BH;
        const __nv_bfloat16* bsL = base + ST_BL;

        #pragma unroll
        for (int ko = 0; ko < BK; ko += 16) {
            uint32_t ah[2][4], al[2][4];
            #pragma unroll
            for (int mt = 0; mt < 2; mt++) {
                int rb = wm * 32 + mt * 16;
                ah[mt][0] = *reinterpret_cast<const uint32_t*>(asH + (rb + g    ) * LDSW + ko + t2    );
                ah[mt][1] = *reinterpret_cast<const uint32_t*>(asH + (rb + g + 8) * LDSW + ko + t2    );
                ah[mt][2] = *reinterpret_cast<const uint32_t*>(asH + (rb + g    ) * LDSW + ko + t2 + 8);
                ah[mt][3] = *reinterpret_cast<const uint32_t*>(asH + (rb + g + 8) * LDSW + ko + t2 + 8);
                al[mt][0] = *reinterpret_cast<const uint32_t*>(asL + (rb + g    ) * LDSW + ko + t2    );
                al[mt][1] = *reinterpret_cast<const uint32_t*>(asL + (rb + g + 8) * LDSW + ko + t2    );
                al[mt][2] = *reinterpret_cast<const uint32_t*>(asL + (rb + g    ) * LDSW + ko + t2 + 8);
                al[mt][3] = *reinterpret_cast<const uint32_t*>(asL + (rb + g + 8) * LDSW + ko + t2 + 8);
            }
            uint32_t bh[NT][2], bl[NT][2];
            #pragma unroll
            for (int nt = 0; nt < NT; nt++) {
                int nb = wn * 32 + nt * 8 + g;
                bh[nt][0] = *reinterpret_cast<const uint32_t*>(bsH + nb * LDSW + ko + t2    );
                bh[nt][1] = *reinterpret_cast<const uint32_t*>(bsH + nb * LDSW + ko + t2 + 8);
                bl[nt][0] = *reinterpret_cast<const uint32_t*>(bsL + nb * LDSW + ko + t2    );
                bl[nt][1] = *reinterpret_cast<const uint32_t*>(bsL + nb * LDSW + ko + t2 + 8);
            }
            #pragma unroll
            for (int mt = 0; mt < 2; mt++)
                #pragma unroll
                for (int nt = 0; nt < NT; nt++) {
                    mma16816(acc[mt][nt], ah[mt], bh[nt]);
                    mma16816(acc[mt][nt], ah[mt], bl[nt]);
                    mma16816(acc[mt][nt], al[mt], bh[nt]);
                }
        }
        __syncthreads();
    }

    #pragma unroll
    for (int mt = 0; mt < 2; mt++) {
        int rbase = row0 + wm * 32 + mt * 16;
        #pragma unroll
        for (int half = 0; half < 2; half++) {
            int r = rbase + g + half * 8;
            if (r >= M) continue;
            #pragma unroll
            for (int nt = 0; nt < NT; nt++) {
                int c = col0 + wn * 32 + nt * 8 + t2;
                float v0 = acc[mt][nt][half * 2 + 0];
                float v1 = acc[mt][nt][half * 2 + 1];
                if (EPI != 1) { v0 += bias[c]; v1 += bias[c + 1]; }
                if (EPI == 0) {
                    __nv_bfloat16 h0, l0, h1, l1;
                    split_bf16(v0, h0, l0);
                    split_bf16(v1, h1, l1);
                    __nv_bfloat162 ph; ph.x = h0; ph.y = h1;
                    __nv_bfloat162 pl; pl.x = l0; pl.y = l1;
                    *reinterpret_cast<__nv_bfloat162*>(&Chi[(size_t)r * Nout + c]) = ph;
                    *reinterpret_cast<__nv_bfloat162*>(&Clo[(size_t)r * Nout + c]) = pl;
                } else {
                    *reinterpret_cast<float2*>(&Cf[(size_t)r * Nout + c]) = make_float2(v0, v1);
                }
            }
        }
    }
}

// ---------------- fused gather aggregation ----------------
__global__ __launch_bounds__(256)
void k_gather(const float* __restrict__ ht, const int2* __restrict__ csr,
              const int* __restrict__ rowptr, const float* __restrict__ dinv,
              const float* __restrict__ b,
              __nv_bfloat16* __restrict__ hhi, __nv_bfloat16* __restrict__ hlo, int n) {
    int warp = (blockIdx.x * blockDim.x + threadIdx.x) >> 5;
    int lane = threadIdx.x & 31;
    if (warp >= n) return;
    int i = warp;

    float di = dinv[i];
    float w0 = di * di;
    const float4* row = reinterpret_cast<const float4*>(ht + (size_t)i * DH);
    float4 a0 = row[lane * 2], a1 = row[lane * 2 + 1];
    float acc[8] = { a0.x * w0, a0.y * w0, a0.z * w0, a0.w * w0,
                     a1.x * w0, a1.y * w0, a1.z * w0, a1.w * w0 };

    int beg = rowptr[i], end = rowptr[i + 1];
    int j = beg;
    for (; j + 1 < end; j += 2) {
        int2 e0 = csr[j], e1 = csr[j + 1];
        const float4* r0 = reinterpret_cast<const float4*>(ht + (size_t)e0.x * DH);
        const float4* r1 = reinterpret_cast<const float4*>(ht + (size_t)e1.x * DH);
        float wa = __int_as_float(e0.y), wb = __int_as_float(e1.y);
        float4 v0 = r0[lane * 2], v1 = r0[lane * 2 + 1];
        float4 u0 = r1[lane * 2], u1 = r1[lane * 2 + 1];
        acc[0] += v0.x * wa; acc[1] += v0.y * wa; acc[2] += v0.z * wa; acc[3] += v0.w * wa;
        acc[4] += v1.x * wa; acc[5] += v1.y * wa; acc[6] += v1.z * wa; acc[7] += v1.w * wa;
        acc[0] += u0.x * wb; acc[1] += u0.y * wb; acc[2] += u0.z * wb; acc[3] += u0.w * wb;
        acc[4] += u1.x * wb; acc[5] += u1.y * wb; acc[6] += u1.z * wb; acc[7] += u1.w * wb;
    }
    if (j < end) {
        int2 e0 = csr[j];
        const float4* r0 = reinterpret_cast<const float4*>(ht + (size_t)e0.x * DH);
        float wa = __int_as_float(e0.y);
        float4 v0 = r0[lane * 2], v1 = r0[lane * 2 + 1];
        acc[0] += v0.x * wa; acc[1] += v0.y * wa; acc[2] += v0.z * wa; acc[3] += v0.w * wa;
        acc[4] += v1.x * wa; acc[5] += v1.y * wa; acc[6] += v1.z * wa; acc[7] += v1.w * wa;
    }

    const float4* bp = reinterpret_cast<const float4*>(b);
    float4 b0 = bp[lane * 2], b1 = bp[lane * 2 + 1];
    float bb[8] = { b0.x, b0.y, b0.z, b0.w, b1.x, b1.y, b1.z, b1.w };

    __nv_bfloat16 hh[8], ll[8];
    #pragma unroll
    for (int q = 0; q < 8; q++) {
        float v = tanhf(acc[q] + bb[q]);
        split_bf16(v, hh[q], ll[q]);
    }
    *reinterpret_cast<uint4*>(hhi + (size_t)i * DH + lane * 8) = *reinterpret_cast<uint4*>(hh);
    *reinterpret_cast<uint4*>(hlo + (size_t)i * DH + lane * 8) = *reinterpret_cast<uint4*>(ll);
}

// ---------------- launcher ----------------
extern "C" void kernel_launch(void* const* d_in, const int* in_sizes, int n_in,
                              void* d_out, int out_size) {
    const float* x      = (const float*)d_in[0];
    const int*   eidx   = (const int*)  d_in[1];
    const float* W_emb  = (const float*)d_in[2];
    const float* b_emb  = (const float*)d_in[3];
    const float* W_conv = (const float*)d_in[4];
    const float* b_conv = (const float*)d_in[5];
    const float* W_out  = (const float*)d_in[6];
    const float* b_out  = (const float*)d_in[7];
    float* out = (float*)d_out;

    int E = in_sizes[1] / 2;
    if (E > E_MAX) E = E_MAX;
    const int* src = eidx;
    const int* dst = eidx + E;
    const int n = N_NODES;

    float *dinv, *ht;
    int *cnt, *partial, *rowptr, *cursor;
    int2 *csr;
    __nv_bfloat16 *xhi, *xlo, *hhi, *hlo;
    __nv_bfloat16 *wembh, *wembl, *wconvh, *wconvl, *wouth, *woutl;
    cudaGetSymbolAddress((void**)&dinv,   g_dinv);
    cudaGetSymbolAddress((void**)&cnt,    g_cnt);
    cudaGetSymbolAddress((void**)&partial,g_partial);
    cudaGetSymbolAddress((void**)&rowptr, g_rowptr);
    cudaGetSymbolAddress((void**)&cursor, g_cursor);
    cudaGetSymbolAddress((void**)&csr,    g_csr);
    cudaGetSymbolAddress((void**)&ht,   g_ht);
    cudaGetSymbolAddress((void**)&xhi,  g_xhi);
    cudaGetSymbolAddress((void**)&xlo,  g_xlo);
    cudaGetSymbolAddress((void**)&hhi,  g_hhi);
    cudaGetSymbolAddress((void**)&hlo,  g_hlo);
    cudaGetSymbolAddress((void**)&wembh, g_wembh);
    cudaGetSymbolAddress((void**)&wembl, g_wembl);
    cudaGetSymbolAddress((void**)&wconvh, g_wconvh);
    cudaGetSymbolAddress((void**)&wconvl, g_wconvl);
    cudaGetSymbolAddress((void**)&wouth, g_wouth);
    cudaGetSymbolAddress((void**)&woutl, g_woutl);

    const int SMEM_GEMM = 2 * STAGE * (int)sizeof(__nv_bfloat16);   // 61440
    cudaFuncSetAttribute(k_mma_gemm<DIN, 0>, cudaFuncAttributeMaxDynamicSharedMemorySize, SMEM_GEMM);
    cudaFuncSetAttribute(k_mma_gemm<DH, 1>,  cudaFuncAttributeMaxDynamicSharedMemorySize, SMEM_GEMM);
    cudaFuncSetAttribute(k_mma_gemm<DH, 2>,  cudaFuncAttributeMaxDynamicSharedMemorySize, SMEM_GEMM);

    // CSR build + dinv
    k_zero <<<(n + 255) / 256, 256>>>(cnt, n);
    k_count<<<(E + 255) / 256, 256>>>(dst, cnt, E);
    k_dinv <<<(n + 255) / 256, 256>>>(cnt, dinv, n);
    k_scan1<<<SCAN_NB, 256>>>(cnt, partial, n);
    k_scan2<<<1, 64>>>(partial, rowptr, SCAN_NB, n);
    k_scan3<<<SCAN_NB, 256>>>(cnt, partial, rowptr, cursor, n);
    k_fill <<<(E + 255) / 256, 256>>>(src, dst, dinv, cursor, csr, E);

    // conversions
    k_conv_x<<<(n * DIN + 255) / 256, 256>>>(x, xhi, xlo, n * DIN);
    k_conv_w<<<(DIN * DH + 255) / 256, 256>>>(W_emb, wembh, wembl, DIN, DH);
    for (int l = 0; l < LAYERS; l++)
        k_conv_w<<<(DH * DH + 255) / 256, 256>>>(W_conv + (size_t)l * DH * DH,
                                                 wconvh + (size_t)l * DH * DH,
                                                 wconvl + (size_t)l * DH * DH, DH, DH);
    k_conv_w<<<(DH * DOUT + 255) / 256, 256>>>(W_out, wouth, woutl, DH, DOUT);

    int gy = (n + 127) / 128;

    // embedding: h = x @ W_emb + b_emb -> bf16 split
    {
        dim3 grid(DH / 64, gy);
        k_mma_gemm<DIN, 0><<<grid, 256, SMEM_GEMM>>>(xhi, xlo, wembh, wembl, b_emb,
                                                     nullptr, hhi, hlo, n, DH);
    }

    int gather_blocks = (n * 32 + 255) / 256;
    for (int l = 0; l < LAYERS; l++) {
        const float* b = b_conv + (size_t)l * DH;
        dim3 grid(DH / 64, gy);
        k_mma_gemm<DH, 1><<<grid, 256, SMEM_GEMM>>>(hhi, hlo,
                                                    wconvh + (size_t)l * DH * DH,
                                                    wconvl + (size_t)l * DH * DH,
                                                    nullptr, ht, nullptr, nullptr, n, DH);
        k_gather<<<gather_blocks, 256>>>(ht, csr, rowptr, dinv, b, hhi, hlo, n);
    }

    // output: out = h @ W_out + b_out
    {
        dim3 grid(DOUT / 64, gy);
        k_mma_gemm<DH, 2><<<grid, 256, SMEM_GEMM>>>(hhi, hlo, wouth, woutl, b_out,
                                                    out, nullptr, nullptr, n, DOUT);
    }
}